// round 4
// baseline (speedup 1.0000x reference)
#include <cuda_runtime.h>

// OpticalFlow dense_image_warp: image [8,512,512,16] f32, flow [8,512,512,2] f32
// out[b,y,x,c] = bilinear sample of image at (y - flow[...,0], x - flow[...,1])
// floor clamped to [0, 510], frac clamped to [0,1] (edge clamp), per reference.
//
// R2: 4 threads/pixel (channel-parallel) -> lane-contiguous gathers.
// R3: 2 x-adjacent pixels per thread -> 9 outstanding loads (1 flow float4 +
//     8 corner LDG.128) to hide DRAM latency; R2 showed nothing saturated
//     (DRAM 58%, L1 59%, issue 28%) = latency-bound.

#define B 8
#define H 512
#define W 512
#define HW (H * W)
#define NPIX (B * HW)
#define NTHREADS_TOTAL (NPIX * 2)   // 4 threads per 2 pixels

__device__ __forceinline__ float4 blend4(float4 tl, float4 tr, float4 bl, float4 br,
                                         float ax, float ay)
{
    float4 r;
    float tp, bt;
    tp = tl.x + ax * (tr.x - tl.x); bt = bl.x + ax * (br.x - bl.x); r.x = tp + ay * (bt - tp);
    tp = tl.y + ax * (tr.y - tl.y); bt = bl.y + ax * (br.y - bl.y); r.y = tp + ay * (bt - tp);
    tp = tl.z + ax * (tr.z - tl.z); bt = bl.z + ax * (br.z - bl.z); r.z = tp + ay * (bt - tp);
    tp = tl.w + ax * (tr.w - tl.w); bt = bl.w + ax * (br.w - bl.w); r.w = tp + ay * (bt - tp);
    return r;
}

__global__ __launch_bounds__(256) void warp_kernel(
    const float* __restrict__ image,
    const float* __restrict__ flow,
    float* __restrict__ out)
{
    int t = blockIdx.x * blockDim.x + threadIdx.x;

    int g  = t & 3;          // channel group 0..3
    int pp = t >> 2;         // pixel-pair index
    int pix0 = pp << 1;      // even pixel; pix1 = pix0+1 (same row: W even)

    int b = pix0 >> 18;
    int p = pix0 & (HW - 1);
    int y = p >> 9;
    int x = p & 511;         // even; x+1 < 512 always

    // both pixels' flow in one float4 (lanes 4k..4k+3 broadcast)
    float4 f = __ldg(((const float4*)flow) + pp);

    // pixel 0
    float qy0 = (float)y - f.x;
    float qx0 = (float)x - f.y;
    float fy0 = fminf(fmaxf(floorf(qy0), 0.0f), (float)(H - 2));
    float fx0 = fminf(fmaxf(floorf(qx0), 0.0f), (float)(W - 2));
    float ay0 = fminf(fmaxf(qy0 - fy0, 0.0f), 1.0f);
    float ax0 = fminf(fmaxf(qx0 - fx0, 0.0f), 1.0f);
    int iy0 = (int)fy0, ix0 = (int)fx0;

    // pixel 1
    float qy1 = (float)y - f.z;
    float qx1 = (float)(x + 1) - f.w;
    float fy1 = fminf(fmaxf(floorf(qy1), 0.0f), (float)(H - 2));
    float fx1 = fminf(fmaxf(floorf(qx1), 0.0f), (float)(W - 2));
    float ay1 = fminf(fmaxf(qy1 - fy1, 0.0f), 1.0f);
    float ax1 = fminf(fmaxf(qx1 - fx1, 0.0f), 1.0f);
    int iy1 = (int)fy1, ix1 = (int)fx1;

    const float4* base = (const float4*)image + (size_t)b * (HW * 4);

    int a_tl = (iy0 * W + ix0) * 4 + g;
    int a_bl = a_tl + W * 4;
    int b_tl = (iy1 * W + ix1) * 4 + g;
    int b_bl = b_tl + W * 4;

    // front-batch all 8 gathers
    float4 tl0 = __ldg(base + a_tl);
    float4 tr0 = __ldg(base + a_tl + 4);
    float4 bl0 = __ldg(base + a_bl);
    float4 br0 = __ldg(base + a_bl + 4);
    float4 tl1 = __ldg(base + b_tl);
    float4 tr1 = __ldg(base + b_tl + 4);
    float4 bl1 = __ldg(base + b_bl);
    float4 br1 = __ldg(base + b_bl + 4);

    float4 r0 = blend4(tl0, tr0, bl0, br0, ax0, ay0);
    float4 r1 = blend4(tl1, tr1, bl1, br1, ax1, ay1);

    // output float4 index: pixel*4 + g; streaming stores (write-once data)
    __stcs(((float4*)out) + ((size_t)pix0 * 4 + g), r0);
    __stcs(((float4*)out) + ((size_t)(pix0 + 1) * 4 + g), r1);
}

extern "C" void kernel_launch(void* const* d_in, const int* in_sizes, int n_in,
                              void* d_out, int out_size)
{
    const float* image = (const float*)d_in[0];
    const float* flow  = (const float*)d_in[1];
    float* out = (float*)d_out;

    int threads = 256;
    int blocks = NTHREADS_TOTAL / threads;   // 16384
    warp_kernel<<<blocks, threads>>>(image, flow, out);
}

// round 6
// speedup vs baseline: 1.0353x; 1.0353x over previous
#include <cuda_runtime.h>

// OpticalFlow dense_image_warp: image [8,512,512,16] f32, flow [8,512,512,2] f32
// out[b,y,x,c] = bilinear sample of image at (y - flow[...,0], x - flow[...,1])
// floor clamped to [0, 510], frac clamped to [0,1] (edge clamp), per reference.
//
// R2: 4 threads/pixel (channel-parallel) -> lane-contiguous gathers.  (59.4us)
// R3: 2 pixels/thread ILP -> REGRESSED (occupancy loss beat ILP gain). Reverted.
// R4: R2 mapping + K=4 grid-stride loop with flow software-prefetch: flow load
//     for iter i+1 overlaps corner gathers of iter i, removing the serial
//     flow->gather latency chain that kept DRAM at 58% / issue at 28%.

#define B 8
#define H 512
#define W 512
#define HW (H * W)
#define NPIX (B * HW)
#define K_ITERS 4
#define TOTAL_T ((NPIX * 4) / K_ITERS)   // 2097152 threads, stride per iter

__global__ __launch_bounds__(256) void warp_kernel(
    const float* __restrict__ image,
    const float* __restrict__ flow,
    float* __restrict__ out)
{
    int t = blockIdx.x * blockDim.x + threadIdx.x;
    const int g = t & 3;     // channel group, invariant across iterations

    // prefetch flow for first iteration
    float2 f = __ldg(((const float2*)flow) + (t >> 2));

#pragma unroll
    for (int i = 0; i < K_ITERS; i++) {
        int tt = t + i * TOTAL_T;

        // prefetch next iteration's flow BEFORE this iteration's gathers
        float2 f_next = f;
        if (i + 1 < K_ITERS)
            f_next = __ldg(((const float2*)flow) + ((tt + TOTAL_T) >> 2));

        int pix = tt >> 2;
        int b = pix >> 18;
        int p = pix & (HW - 1);
        int y = p >> 9;
        int x = p & 511;

        float qy = (float)y - f.x;
        float qx = (float)x - f.y;

        float fy = fminf(fmaxf(floorf(qy), 0.0f), (float)(H - 2));
        float fx = fminf(fmaxf(floorf(qx), 0.0f), (float)(W - 2));
        float ay = fminf(fmaxf(qy - fy, 0.0f), 1.0f);
        float ax = fminf(fmaxf(qx - fx, 0.0f), 1.0f);
        int iy = (int)fy;
        int ix = (int)fx;

        const float4* base = (const float4*)image + (size_t)b * (HW * 4);
        int o_tl = (iy * W + ix) * 4 + g;
        int o_bl = o_tl + W * 4;

        float4 tl = __ldg(base + o_tl);
        float4 tr = __ldg(base + o_tl + 4);
        float4 bl = __ldg(base + o_bl);
        float4 br = __ldg(base + o_bl + 4);

        float4 r;
        float tp, bt;
        tp = tl.x + ax * (tr.x - tl.x); bt = bl.x + ax * (br.x - bl.x); r.x = tp + ay * (bt - tp);
        tp = tl.y + ax * (tr.y - tl.y); bt = bl.y + ax * (br.y - bl.y); r.y = tp + ay * (bt - tp);
        tp = tl.z + ax * (tr.z - tl.z); bt = bl.z + ax * (br.z - bl.z); r.z = tp + ay * (bt - tp);
        tp = tl.w + ax * (tr.w - tl.w); bt = bl.w + ax * (br.w - bl.w); r.w = tp + ay * (bt - tp);

        __stcs(((float4*)out) + tt, r);

        f = f_next;
    }
}

extern "C" void kernel_launch(void* const* d_in, const int* in_sizes, int n_in,
                              void* d_out, int out_size)
{
    const float* image = (const float*)d_in[0];
    const float* flow  = (const float*)d_in[1];
    float* out = (float*)d_out;

    int threads = 256;
    int blocks = TOTAL_T / threads;   // 8192
    warp_kernel<<<blocks, threads>>>(image, flow, out);
}